// round 4
// baseline (speedup 1.0000x reference)
#include <cuda_runtime.h>
#include <cstddef>

// ScaledDotProductAttention: B=2,H=16,S=2048,D=64 fp32.
// attn_bias is per-query (broadcast over keys) -> softmax-invariant -> ignored.
// Flash-attention, fp32 compute via packed f32x2 FMA (FFMA2), one query per thread.

typedef unsigned long long u64;

__device__ __forceinline__ u64 pack2(float x, float y) {
    u64 r; asm("mov.b64 %0, {%1, %2};" : "=l"(r) : "f"(x), "f"(y)); return r;
}
__device__ __forceinline__ float2 unpack2(u64 a) {
    float2 r; asm("mov.b64 {%0, %1}, %2;" : "=f"(r.x), "=f"(r.y) : "l"(a)); return r;
}
__device__ __forceinline__ u64 fma2(u64 a, u64 b, u64 c) {
    u64 d; asm("fma.rn.f32x2 %0, %1, %2, %3;" : "=l"(d) : "l"(a), "l"(b), "l"(c)); return d;
}
__device__ __forceinline__ u64 mul2(u64 a, u64 b) {
    u64 d; asm("mul.rn.f32x2 %0, %1, %2;" : "=l"(d) : "l"(a), "l"(b)); return d;
}
__device__ __forceinline__ u64 add2(u64 a, u64 b) {
    u64 d; asm("add.rn.f32x2 %0, %1, %2;" : "=l"(d) : "l"(a), "l"(b)); return d;
}
__device__ __forceinline__ float ex2(float x) {
    float r; asm("ex2.approx.ftz.f32 %0, %1;" : "=f"(r) : "f"(x)); return r;
}

static constexpr int D   = 64;
static constexpr int DP2 = D / 2;   // 32 packed pairs
static constexpr int Br  = 128;     // queries per CTA (= threads)
static constexpr int Bc  = 32;      // keys per tile
static constexpr int SEQ = 2048;

__global__ __launch_bounds__(Br)
void attn_kernel(const float* __restrict__ Q,
                 const float* __restrict__ K,
                 const float* __restrict__ V,
                 float* __restrict__ O)
{
    __shared__ float sK[Bc * D];
    __shared__ float sV[Bc * D];

    const int bh  = blockIdx.y;
    const int q0  = blockIdx.x * Br;
    const int tid = threadIdx.x;
    const size_t headoff = (size_t)bh * SEQ * D;

    // Load my query row, pre-scaled by D^-1/2 * log2(e) so we can use exp2.
    const float qscale = 0.125f * 1.4426950408889634f;
    const float2* qrow = reinterpret_cast<const float2*>(Q + headoff + (size_t)(q0 + tid) * D);
    u64 qp[DP2];
#pragma unroll
    for (int i = 0; i < DP2; i++) {
        float2 f = qrow[i];
        qp[i] = pack2(f.x * qscale, f.y * qscale);
    }

    u64 o2[DP2];
#pragma unroll
    for (int i = 0; i < DP2; i++) o2[i] = 0ull;   // packed (0,0)
    float m = -1e30f, l = 0.0f;

    const float* kbase = K + headoff;
    const float* vbase = V + headoff;

    for (int kt = 0; kt < SEQ; kt += Bc) {
        // --- Stage K/V tile (Bc x D fp32 each) into smem, coalesced float4 ---
        const float4* kg = reinterpret_cast<const float4*>(kbase + (size_t)kt * D);
        const float4* vg = reinterpret_cast<const float4*>(vbase + (size_t)kt * D);
        float4* k4 = reinterpret_cast<float4*>(sK);
        float4* v4 = reinterpret_cast<float4*>(sV);
#pragma unroll
        for (int u = 0; u < (Bc * D / 4) / Br; u++) {   // 512/128 = 4
            k4[tid + Br * u] = kg[tid + Br * u];
            v4[tid + Br * u] = vg[tid + Br * u];
        }
        __syncthreads();

        // --- Scores: s_j = q . k_j  (K reads are warp-uniform -> smem broadcast) ---
        float sreg[Bc];
#pragma unroll
        for (int j = 0; j < Bc; j++) {
            const u64* krow = reinterpret_cast<const u64*>(sK + j * D);
            u64 a0 = 0ull, a1 = 0ull, a2 = 0ull, a3 = 0ull;
#pragma unroll
            for (int i = 0; i < DP2; i += 4) {
                a0 = fma2(qp[i + 0], krow[i + 0], a0);
                a1 = fma2(qp[i + 1], krow[i + 1], a1);
                a2 = fma2(qp[i + 2], krow[i + 2], a2);
                a3 = fma2(qp[i + 3], krow[i + 3], a3);
            }
            u64 t = add2(add2(a0, a1), add2(a2, a3));
            float2 f = unpack2(t);
            sreg[j] = f.x + f.y;
        }

        // --- Online softmax update ---
        float mt = sreg[0];
#pragma unroll
        for (int j = 1; j < Bc; j++) mt = fmaxf(mt, sreg[j]);
        float mnew = fmaxf(m, mt);
        float corr = ex2(m - mnew);
        l *= corr;
        u64 corr2 = pack2(corr, corr);
#pragma unroll
        for (int i = 0; i < DP2; i++) o2[i] = mul2(o2[i], corr2);

        // --- PV accumulate (V reads also warp-uniform broadcast) ---
#pragma unroll
        for (int j = 0; j < Bc; j++) {
            float p = ex2(sreg[j] - mnew);
            l += p;
            u64 p2 = pack2(p, p);
            const u64* vrow = reinterpret_cast<const u64*>(sV + j * D);
#pragma unroll
            for (int i = 0; i < DP2; i++) o2[i] = fma2(p2, vrow[i], o2[i]);
        }
        m = mnew;
        __syncthreads();
    }

    // --- Normalize and write out ---
    float inv = 1.0f / l;
    u64 inv2 = pack2(inv, inv);
    float* orow = O + headoff + (size_t)(q0 + tid) * D;
#pragma unroll
    for (int i = 0; i < DP2; i++) {
        u64 r = mul2(o2[i], inv2);
        reinterpret_cast<u64*>(orow)[i] = r;
    }
}

extern "C" void kernel_launch(void* const* d_in, const int* in_sizes, int n_in,
                              void* d_out, int out_size)
{
    const float* q = (const float*)d_in[0];
    const float* k = (const float*)d_in[1];
    const float* v = (const float*)d_in[2];
    // d_in[3] = attn_bias: per-query constant added across the key axis ->
    // softmax-invariant -> intentionally unused.
    float* out = (float*)d_out;

    const int BH = in_sizes[0] / (SEQ * D);   // B*H = 32 for this problem
    dim3 grid(SEQ / Br, BH);
    attn_kernel<<<grid, Br>>>(q, k, v, out);
}

// round 14
// speedup vs baseline: 1.0022x; 1.0022x over previous
#include <cuda_runtime.h>
#include <cstddef>

// ScaledDotProductAttention: B=2,H=16,S=2048,D=64 fp32.
// attn_bias is per-query (broadcast over keys) -> softmax-invariant -> ignored.
// Flash-attention, fp32 via packed f32x2 FMA. R4 finding: kernel was LDS-issue
// bound (1:1 LDS.64:FFMA2, L1=81.5%). R5: LDS.128 smem reads -> 1 LDS per 2 FFMA2.

typedef unsigned long long u64;

__device__ __forceinline__ u64 pack2(float x, float y) {
    u64 r; asm("mov.b64 %0, {%1, %2};" : "=l"(r) : "f"(x), "f"(y)); return r;
}
__device__ __forceinline__ float2 unpack2(u64 a) {
    float2 r; asm("mov.b64 {%0, %1}, %2;" : "=f"(r.x), "=f"(r.y) : "l"(a)); return r;
}
__device__ __forceinline__ u64 fma2(u64 a, u64 b, u64 c) {
    u64 d; asm("fma.rn.f32x2 %0, %1, %2, %3;" : "=l"(d) : "l"(a), "l"(b), "l"(c)); return d;
}
__device__ __forceinline__ u64 mul2(u64 a, u64 b) {
    u64 d; asm("mul.rn.f32x2 %0, %1, %2;" : "=l"(d) : "l"(a), "l"(b)); return d;
}
__device__ __forceinline__ u64 add2(u64 a, u64 b) {
    u64 d; asm("add.rn.f32x2 %0, %1, %2;" : "=l"(d) : "l"(a), "l"(b)); return d;
}
__device__ __forceinline__ float ex2(float x) {
    float r; asm("ex2.approx.ftz.f32 %0, %1;" : "=f"(r) : "f"(x)); return r;
}

static constexpr int D   = 64;
static constexpr int DP2 = D / 2;   // 32 packed pairs
static constexpr int DP4 = D / 4;   // 16 float4 per row
static constexpr int Br  = 128;     // queries per CTA (= threads)
static constexpr int Bc  = 32;      // keys per tile
static constexpr int SEQ = 2048;

__global__ __launch_bounds__(Br)
void attn_kernel(const float* __restrict__ Q,
                 const float* __restrict__ K,
                 const float* __restrict__ V,
                 float* __restrict__ O)
{
    __shared__ float4 sK[Bc * DP4];
    __shared__ float4 sV[Bc * DP4];

    const int bh  = blockIdx.y;
    const int q0  = blockIdx.x * Br;
    const int tid = threadIdx.x;
    const size_t headoff = (size_t)bh * SEQ * D;

    // Load my query row, pre-scaled by D^-1/2 * log2(e) so we can use exp2.
    const float qscale = 0.125f * 1.4426950408889634f;
    const float2* qrow = reinterpret_cast<const float2*>(Q + headoff + (size_t)(q0 + tid) * D);
    u64 qp[DP2];
#pragma unroll
    for (int i = 0; i < DP2; i++) {
        float2 f = qrow[i];
        qp[i] = pack2(f.x * qscale, f.y * qscale);
    }

    u64 o2[DP2];
#pragma unroll
    for (int i = 0; i < DP2; i++) o2[i] = 0ull;   // packed (0,0)
    float m = -1e30f, l = 0.0f;

    const float4* kbase = reinterpret_cast<const float4*>(K + headoff);
    const float4* vbase = reinterpret_cast<const float4*>(V + headoff);

    for (int kt = 0; kt < SEQ; kt += Bc) {
        // --- Stage K/V tile (Bc x D fp32 each) into smem, coalesced float4 ---
#pragma unroll
        for (int u = 0; u < (Bc * DP4) / Br; u++) {   // 512/128 = 4
            sK[tid + Br * u] = kbase[kt * DP4 + tid + Br * u];
            sV[tid + Br * u] = vbase[kt * DP4 + tid + Br * u];
        }
        __syncthreads();

        // --- Scores: s_j = q . k_j ; smem reads are 128-bit warp-uniform broadcasts ---
        float sreg[Bc];
#pragma unroll
        for (int j = 0; j < Bc; j++) {
            const float4* krow = sK + j * DP4;
            u64 a0 = 0ull, a1 = 0ull, a2 = 0ull, a3 = 0ull;
#pragma unroll
            for (int i = 0; i < DP4; i += 2) {          // 2 float4 = 4 u64 per iter
                float4 f0 = krow[i + 0];
                float4 f1 = krow[i + 1];
                a0 = fma2(qp[2*i + 0], pack2(f0.x, f0.y), a0);
                a1 = fma2(qp[2*i + 1], pack2(f0.z, f0.w), a1);
                a2 = fma2(qp[2*i + 2], pack2(f1.x, f1.y), a2);
                a3 = fma2(qp[2*i + 3], pack2(f1.z, f1.w), a3);
            }
            u64 t = add2(add2(a0, a1), add2(a2, a3));
            float2 f = unpack2(t);
            sreg[j] = f.x + f.y;
        }

        // --- Online softmax update ---
        float mt = sreg[0];
#pragma unroll
        for (int j = 1; j < Bc; j++) mt = fmaxf(mt, sreg[j]);
        float mnew = fmaxf(m, mt);
        float corr = ex2(m - mnew);
        l *= corr;
        u64 corr2 = pack2(corr, corr);
#pragma unroll
        for (int i = 0; i < DP2; i++) o2[i] = mul2(o2[i], corr2);

        // --- PV accumulate (128-bit broadcast V reads) ---
#pragma unroll
        for (int j = 0; j < Bc; j++) {
            float p = ex2(sreg[j] - mnew);
            l += p;
            u64 p2 = pack2(p, p);
            const float4* vrow = sV + j * DP4;
#pragma unroll
            for (int i = 0; i < DP4; i++) {
                float4 f = vrow[i];
                o2[2*i + 0] = fma2(p2, pack2(f.x, f.y), o2[2*i + 0]);
                o2[2*i + 1] = fma2(p2, pack2(f.z, f.w), o2[2*i + 1]);
            }
        }
        m = mnew;
        __syncthreads();
    }

    // --- Normalize and write out (128-bit stores) ---
    float inv = 1.0f / l;
    u64 inv2 = pack2(inv, inv);
    float4* orow = reinterpret_cast<float4*>(O + headoff + (size_t)(q0 + tid) * D);
#pragma unroll
    for (int i = 0; i < DP4; i++) {
        float2 lo = unpack2(mul2(o2[2*i + 0], inv2));
        float2 hi = unpack2(mul2(o2[2*i + 1], inv2));
        orow[i] = make_float4(lo.x, lo.y, hi.x, hi.y);
    }
}

extern "C" void kernel_launch(void* const* d_in, const int* in_sizes, int n_in,
                              void* d_out, int out_size)
{
    const float* q = (const float*)d_in[0];
    const float* k = (const float*)d_in[1];
    const float* v = (const float*)d_in[2];
    // d_in[3] = attn_bias: per-query constant added across the key axis ->
    // softmax-invariant -> intentionally unused.
    float* out = (float*)d_out;

    const int BH = in_sizes[0] / (SEQ * D);   // B*H = 32 for this problem
    dim3 grid(SEQ / Br, BH);
    attn_kernel<<<grid, Br>>>(q, k, v, out);
}